// round 14
// baseline (speedup 1.0000x reference)
#include <cuda_runtime.h>

// PlasticSynapse: out = clip(baseline*a + w*(1-a) + R*|kappa|*(post*pre + s*noise), 0, 1)
// Shapes: w,noise,out: [B=64, OUT=1024, IN=1024]; baseline,kappa: [OUT,IN];
//         R: [B]; pre: [B,IN]; post: [B,OUT].
// HBM-bound elementwise: 768 MiB compulsory traffic (verified minimal).
// R9  (256thr, 1x f4, stcs): 115.1us @ 87.4% DRAM
// R10 (4x strided):          122.9us FAILED
// R11 (128thr, 1x f4, stcs): 114.9us @ 87.1% DRAM  <- best
// R12 (st.global.wt):        118.3us FAILED (WT loses L2 write coalescing)
// R14: ITEMS=2 ADJACENT float4 per thread (32B/stream/thread). Same (b,o) both
//      items -> post/R once; halves per-byte instruction overhead. If neutral or
//      worse, the mixed-stream DRAM ceiling is confirmed and R11 is final.

#define B_   64
#define OUT_ 1024
#define IN_  1024
#define IN4_ (IN_ / 4)          // 256 float4 per row
#define TOTAL4 ((B_ * OUT_ * IN_) / 4)
#define ALPHA_W   0.01f
#define ONE_M_A   0.99f
#define SIGMA_W   0.14142135623730953f

__device__ __forceinline__ float4 psyn_elem(float4 w4, float4 n4,
                                            float4 bl, float4 kp,
                                            float4 pr, float r, float p)
{
    float4 res;
    res.x = __saturatef(fmaf(bl.x, ALPHA_W, fmaf(w4.x, ONE_M_A,
                r * fabsf(kp.x) * fmaf(SIGMA_W, n4.x, p * pr.x))));
    res.y = __saturatef(fmaf(bl.y, ALPHA_W, fmaf(w4.y, ONE_M_A,
                r * fabsf(kp.y) * fmaf(SIGMA_W, n4.y, p * pr.y))));
    res.z = __saturatef(fmaf(bl.z, ALPHA_W, fmaf(w4.z, ONE_M_A,
                r * fabsf(kp.z) * fmaf(SIGMA_W, n4.z, p * pr.z))));
    res.w = __saturatef(fmaf(bl.w, ALPHA_W, fmaf(w4.w, ONE_M_A,
                r * fabsf(kp.w) * fmaf(SIGMA_W, n4.w, p * pr.w))));
    return res;
}

__global__ __launch_bounds__(128)
void plastic_synapse_kernel(const float4* __restrict__ w,
                            const float4* __restrict__ baseline,
                            const float*  __restrict__ R,
                            const float4* __restrict__ pre,
                            const float*  __restrict__ post,
                            const float4* __restrict__ kappa,
                            const float4* __restrict__ noise,
                            float4*       __restrict__ out)
{
    // Two ADJACENT float4s per thread: idx and idx+1 (idx even).
    const int idx = (blockIdx.x * blockDim.x + threadIdx.x) * 2;
    // idx = ((b * OUT_) + o) * IN4_ + i4 ; idx even -> idx+1 stays in same row.
    const int i4 = idx & (IN4_ - 1);
    const int o  = (idx >> 8) & (OUT_ - 1);
    const int b  = idx >> 18;

    // Streamed (read-once) operands: evict-first, front-batched (4 LDG.128).
    const float4 w0 = __ldcs(&w[idx]);
    const float4 w1 = __ldcs(&w[idx + 1]);
    const float4 n0 = __ldcs(&noise[idx]);
    const float4 n1 = __ldcs(&noise[idx + 1]);

    // Reused operands (L2-resident, 8 MiB total).
    const int oi = o * IN4_ + i4;
    const float4 bl0 = __ldg(&baseline[oi]);
    const float4 bl1 = __ldg(&baseline[oi + 1]);
    const float4 kp0 = __ldg(&kappa[oi]);
    const float4 kp1 = __ldg(&kappa[oi + 1]);
    const int pi = b * IN4_ + i4;
    const float4 pr0 = __ldg(&pre[pi]);
    const float4 pr1 = __ldg(&pre[pi + 1]);
    const float  r   = __ldg(&R[b]);
    const float  p   = __ldg(&post[b * OUT_ + o]);

    __stcs(&out[idx    ], psyn_elem(w0, n0, bl0, kp0, pr0, r, p));
    __stcs(&out[idx + 1], psyn_elem(w1, n1, bl1, kp1, pr1, r, p));
}

extern "C" void kernel_launch(void* const* d_in, const int* in_sizes, int n_in,
                              void* d_out, int out_size)
{
    // metadata order: w, baseline, R, pre, post, kappa, noise
    const float4* w        = (const float4*)d_in[0];
    const float4* baseline = (const float4*)d_in[1];
    const float*  R        = (const float*) d_in[2];
    const float4* pre      = (const float4*)d_in[3];
    const float*  post     = (const float*) d_in[4];
    const float4* kappa    = (const float4*)d_in[5];
    const float4* noise    = (const float4*)d_in[6];
    float4*       out      = (float4*)d_out;

    const int threads = 128;
    const int blocks  = (TOTAL4 / 2) / threads;   // 65,536 blocks

    plastic_synapse_kernel<<<blocks, threads>>>(w, baseline, R, pre, post,
                                                kappa, noise, out);
}

// round 15
// speedup vs baseline: 1.1009x; 1.1009x over previous
#include <cuda_runtime.h>

// PlasticSynapse: out = clip(baseline*a + w*(1-a) + R*|kappa|*(post*pre + s*noise), 0, 1)
// Shapes: w,noise,out: [B=64, OUT=1024, IN=1024]; baseline,kappa: [OUT,IN];
//         R: [B]; pre: [B,IN]; post: [B,OUT].
// HBM-bound elementwise: 768 MiB compulsory traffic (verified minimal).
//
// FINAL = R11 config. Experiment history:
//   R9  (256thr, 1x f4, stcs):  115.1us @ 87.4% DRAM
//   R10 (4x f4 strided/thread): 122.9us FAILED (regs 44, occ 54%)
//   R11 (128thr, 1x f4, stcs):  114.9us @ 87.1% DRAM, occ 85%  <- BEST
//   R12 (st.global.wt):         118.3us FAILED (loses L2 write coalescing)
//   R14 (2x f4 adjacent):       127.1us FAILED (intra-warp coalescing broken,
//                                L1 wavefronts 2x, L1=77%)
// Conclusion: one warp-contiguous float4 per thread + __ldcs streams +
// L2-resident baseline/kappa is at the 2:1 read/write mixed-stream DRAM
// ceiling (~6.9 TB/s). No SM-side resource binds. Locked.

#define B_   64
#define OUT_ 1024
#define IN_  1024
#define IN4_ (IN_ / 4)          // 256 float4 per row
#define TOTAL4 ((B_ * OUT_ * IN_) / 4)
#define ALPHA_W   0.01f
#define ONE_M_A   0.99f
#define SIGMA_W   0.14142135623730953f

__global__ __launch_bounds__(128)
void plastic_synapse_kernel(const float4* __restrict__ w,
                            const float4* __restrict__ baseline,
                            const float*  __restrict__ R,
                            const float4* __restrict__ pre,
                            const float*  __restrict__ post,
                            const float4* __restrict__ kappa,
                            const float4* __restrict__ noise,
                            float4*       __restrict__ out)
{
    const int idx = blockIdx.x * blockDim.x + threadIdx.x;   // float4 index
    // idx = ((b * OUT_) + o) * IN4_ + i4 ; all powers of two.
    const int i4 = idx & (IN4_ - 1);
    const int o  = (idx >> 8) & (OUT_ - 1);
    const int b  = idx >> 18;

    // Streamed (read-once) operands: evict-first, front-batched.
    const float4 w4 = __ldcs(&w[idx]);
    const float4 n4 = __ldcs(&noise[idx]);

    // Reused operands: L2-resident (8 MiB total), default caching.
    const int oi = o * IN4_ + i4;
    const float4 bl = __ldg(&baseline[oi]);
    const float4 kp = __ldg(&kappa[oi]);
    const float4 pr = __ldg(&pre[b * IN4_ + i4]);
    const float  r  = __ldg(&R[b]);
    const float  p  = __ldg(&post[b * OUT_ + o]);

    float4 res;
    {
        float plas = r * fabsf(kp.x) * fmaf(SIGMA_W, n4.x, p * pr.x);
        res.x = __saturatef(fmaf(bl.x, ALPHA_W, fmaf(w4.x, ONE_M_A, plas)));
    }
    {
        float plas = r * fabsf(kp.y) * fmaf(SIGMA_W, n4.y, p * pr.y);
        res.y = __saturatef(fmaf(bl.y, ALPHA_W, fmaf(w4.y, ONE_M_A, plas)));
    }
    {
        float plas = r * fabsf(kp.z) * fmaf(SIGMA_W, n4.z, p * pr.z);
        res.z = __saturatef(fmaf(bl.z, ALPHA_W, fmaf(w4.z, ONE_M_A, plas)));
    }
    {
        float plas = r * fabsf(kp.w) * fmaf(SIGMA_W, n4.w, p * pr.w);
        res.w = __saturatef(fmaf(bl.w, ALPHA_W, fmaf(w4.w, ONE_M_A, plas)));
    }

    __stcs(&out[idx], res);
}

extern "C" void kernel_launch(void* const* d_in, const int* in_sizes, int n_in,
                              void* d_out, int out_size)
{
    // metadata order: w, baseline, R, pre, post, kappa, noise
    const float4* w        = (const float4*)d_in[0];
    const float4* baseline = (const float4*)d_in[1];
    const float*  R        = (const float*) d_in[2];
    const float4* pre      = (const float4*)d_in[3];
    const float*  post     = (const float*) d_in[4];
    const float4* kappa    = (const float4*)d_in[5];
    const float4* noise    = (const float4*)d_in[6];
    float4*       out      = (float4*)d_out;

    const int threads = 128;
    const int blocks  = TOTAL4 / threads;   // 131,072 blocks

    plastic_synapse_kernel<<<blocks, threads>>>(w, baseline, R, pre, post,
                                                kappa, noise, out);
}

// round 16
// speedup vs baseline: 1.1071x; 1.0056x over previous
#include <cuda_runtime.h>

// PlasticSynapse: out = clip(baseline*a + w*(1-a) + R*|kappa|*(post*pre + s*noise), 0, 1)
// Shapes: w,noise,out: [B=64, OUT=1024, IN=1024]; baseline,kappa: [OUT,IN];
//         R: [B]; pre: [B,IN]; post: [B,OUT].
// HBM-bound elementwise: 768 MiB compulsory traffic (verified minimal).
//
// FINAL = R11 config. Experiment history:
//   R9  (256thr, 1x f4, stcs):  115.1us @ 87.4% DRAM
//   R10 (4x f4 strided/thread): 122.9us FAILED (regs 44, occ 54%)
//   R11 (128thr, 1x f4, stcs):  114.9us @ 87.1% DRAM, occ 85%  <- BEST
//   R12 (st.global.wt):         118.3us FAILED (loses L2 write coalescing)
//   R14 (2x f4 adjacent):       127.1us FAILED (intra-warp coalescing broken,
//                                L1 wavefronts 2x, L1=77%)
// Conclusion: one warp-contiguous float4 per thread + __ldcs streams +
// L2-resident baseline/kappa is at the 2:1 read/write mixed-stream DRAM
// ceiling (~6.9 TB/s). No SM-side resource binds. Locked.

#define B_   64
#define OUT_ 1024
#define IN_  1024
#define IN4_ (IN_ / 4)          // 256 float4 per row
#define TOTAL4 ((B_ * OUT_ * IN_) / 4)
#define ALPHA_W   0.01f
#define ONE_M_A   0.99f
#define SIGMA_W   0.14142135623730953f

__global__ __launch_bounds__(128)
void plastic_synapse_kernel(const float4* __restrict__ w,
                            const float4* __restrict__ baseline,
                            const float*  __restrict__ R,
                            const float4* __restrict__ pre,
                            const float*  __restrict__ post,
                            const float4* __restrict__ kappa,
                            const float4* __restrict__ noise,
                            float4*       __restrict__ out)
{
    const int idx = blockIdx.x * blockDim.x + threadIdx.x;   // float4 index
    // idx = ((b * OUT_) + o) * IN4_ + i4 ; all powers of two.
    const int i4 = idx & (IN4_ - 1);
    const int o  = (idx >> 8) & (OUT_ - 1);
    const int b  = idx >> 18;

    // Streamed (read-once) operands: evict-first, front-batched.
    const float4 w4 = __ldcs(&w[idx]);
    const float4 n4 = __ldcs(&noise[idx]);

    // Reused operands: L2-resident (8 MiB total), default caching.
    const int oi = o * IN4_ + i4;
    const float4 bl = __ldg(&baseline[oi]);
    const float4 kp = __ldg(&kappa[oi]);
    const float4 pr = __ldg(&pre[b * IN4_ + i4]);
    const float  r  = __ldg(&R[b]);
    const float  p  = __ldg(&post[b * OUT_ + o]);

    float4 res;
    {
        float plas = r * fabsf(kp.x) * fmaf(SIGMA_W, n4.x, p * pr.x);
        res.x = __saturatef(fmaf(bl.x, ALPHA_W, fmaf(w4.x, ONE_M_A, plas)));
    }
    {
        float plas = r * fabsf(kp.y) * fmaf(SIGMA_W, n4.y, p * pr.y);
        res.y = __saturatef(fmaf(bl.y, ALPHA_W, fmaf(w4.y, ONE_M_A, plas)));
    }
    {
        float plas = r * fabsf(kp.z) * fmaf(SIGMA_W, n4.z, p * pr.z);
        res.z = __saturatef(fmaf(bl.z, ALPHA_W, fmaf(w4.z, ONE_M_A, plas)));
    }
    {
        float plas = r * fabsf(kp.w) * fmaf(SIGMA_W, n4.w, p * pr.w);
        res.w = __saturatef(fmaf(bl.w, ALPHA_W, fmaf(w4.w, ONE_M_A, plas)));
    }

    __stcs(&out[idx], res);
}

extern "C" void kernel_launch(void* const* d_in, const int* in_sizes, int n_in,
                              void* d_out, int out_size)
{
    // metadata order: w, baseline, R, pre, post, kappa, noise
    const float4* w        = (const float4*)d_in[0];
    const float4* baseline = (const float4*)d_in[1];
    const float*  R        = (const float*) d_in[2];
    const float4* pre      = (const float4*)d_in[3];
    const float*  post     = (const float*) d_in[4];
    const float4* kappa    = (const float4*)d_in[5];
    const float4* noise    = (const float4*)d_in[6];
    float4*       out      = (float4*)d_out;

    const int threads = 128;
    const int blocks  = TOTAL4 / threads;   // 131,072 blocks

    plastic_synapse_kernel<<<blocks, threads>>>(w, baseline, R, pre, post,
                                                kappa, noise, out);
}